// round 16
// baseline (speedup 1.0000x reference)
#include <cuda_runtime.h>

// DropBlock, persistent-grid fused kernel:
//   592 CTAs = 4/SM x 148 SMs (reg-limit max @64 regs). Each CTA:
//   1. front-batches its FIRST tile's 8 float4 x loads (before any barrier)
//   2. computes the mask ONCE (stage u -> bit-parallel separable dilation ->
//      shuffle-reduced popcount sum -> mask*scale float4s in shared)
//   3. grid-strides over tile-blocks: consume current 8, front-batch next 8
//      -> steady state == pure streaming apply kernel, mask via LDS.
// Prologue instances: 3136 -> 592. No wave-transition churn.
// GAMMA = 0.1/49 * (56^2/50^2) = 0.00256 exactly.

#define H 56
#define W 56
#define HW 3136          // 56*56
#define HW4 784          // HW/4
#define GAMMA 0.00256f
#define THREADS 256
#define V4 8
#define V4_PER_TILE (THREADS * V4)   // 2048
#define N_TILES 3136                 // 6,422,528 / 2048
#define GRID 592                     // 4 CTAs/SM * 148 SMs

__global__ void __launch_bounds__(THREADS) dropblock_persist(
    const float4* __restrict__ x, const float4* __restrict__ u4,
    float4* __restrict__ out) {
    // 12.5KB buffer reused: u floats (prologue) then mask float4s (loop)
    __shared__ __align__(16) float s_buf[HW];
    __shared__ unsigned long long rowd[H];
    __shared__ unsigned long long dil[H];
    __shared__ int partial[2];

    const int tid = threadIdx.x;

    // ── 1. front-batch first tile's 8 stream loads (before any barrier) ──
    int tile = blockIdx.x;
    int base = tile * V4_PER_TILE + tid;
    float4 v[V4];
    #pragma unroll
    for (int k = 0; k < V4; ++k)
        v[k] = __ldcs(&x[base + k * THREADS]);

    // ── 2. stage u into shared (784 float4 over 256 threads, coalesced) ──
    float4* s_buf4 = reinterpret_cast<float4*>(s_buf);
    #pragma unroll
    for (int j = 0; j < 4; ++j) {
        const int i = tid + j * THREADS;
        if (i < HW4) s_buf4[i] = __ldg(&u4[i]);
    }
    __syncthreads();

    // ── 3. row-wise backward dilation (width 7) as bit ops ──
    if (tid < H) {
        unsigned long long s = 0ULL;
        #pragma unroll
        for (int w = 0; w < W; ++w)
            s |= (unsigned long long)(s_buf[tid * W + w] < GAMMA) << w;
        unsigned long long a = s | (s << 1);     // shifts {0,1}
        unsigned long long b = a | (a << 2);     // shifts {0..3}
        unsigned long long c = b | (b << 3);     // shifts {0..6}
        rowd[tid] = c & ((1ULL << W) - 1ULL);
    }
    __syncthreads();

    // ── 4. column phase + shuffle-reduced popcount sum (two FULL warps) ──
    if (tid < 64) {
        int p = 0;
        if (tid < H) {
            const int h0 = tid - 6 < 0 ? 0 : tid - 6;
            unsigned long long d = 0ULL;
            for (int h = h0; h <= tid; ++h) d |= rowd[h];
            dil[tid] = d;
            p = __popcll(d);
        }
        #pragma unroll
        for (int off = 16; off > 0; off >>= 1)
            p += __shfl_down_sync(0xFFFFFFFFu, p, off);
        if ((tid & 31) == 0) partial[tid >> 5] = p;
    }
    __syncthreads();

    // ── 5. scale + mask float4s over dead u buffer ──
    const float scale = (float)HW / (float)(HW - partial[0] - partial[1]);
    #pragma unroll
    for (int j = 0; j < 4; ++j) {
        const int s4 = tid + j * THREADS;
        if (s4 < HW4) {
            const int h = s4 / 14;               // 14 float4 per row
            const int w0 = (s4 % 14) * 4;
            const unsigned long long bits = dil[h] >> w0;
            float4 mk;
            mk.x = (bits & 1ULL) ? 0.0f : scale;
            mk.y = (bits & 2ULL) ? 0.0f : scale;
            mk.z = (bits & 4ULL) ? 0.0f : scale;
            mk.w = (bits & 8ULL) ? 0.0f : scale;
            s_buf4[s4] = mk;
        }
    }
    __syncthreads();

    // ── 6. persistent loop: consume current tile, front-batch next ──
    while (true) {
        const int next_tile = tile + GRID;
        const int next_base = next_tile * V4_PER_TILE + tid;
        float4 w[V4];
        const bool more = next_tile < N_TILES;
        if (more) {
            #pragma unroll
            for (int k = 0; k < V4; ++k)
                w[k] = __ldcs(&x[next_base + k * THREADS]);
        }

        int s4 = base % HW4;                     // incremental wrap
        #pragma unroll
        for (int k = 0; k < V4; ++k) {
            const float4 mk = s_buf4[s4];
            v[k].x *= mk.x; v[k].y *= mk.y; v[k].z *= mk.z; v[k].w *= mk.w;
            __stcs(&out[base + k * THREADS], v[k]);
            s4 += THREADS;
            if (s4 >= HW4) s4 -= HW4;
        }

        if (!more) break;
        tile = next_tile;
        base = next_base;
        #pragma unroll
        for (int k = 0; k < V4; ++k) v[k] = w[k];
    }
}

extern "C" void kernel_launch(void* const* d_in, const int* in_sizes, int n_in,
                              void* d_out, int out_size) {
    const float* x = (const float*)d_in[0];   // (32,256,56,56) f32
    const float* u = (const float*)d_in[1];   // (56,56) f32

    dropblock_persist<<<GRID, THREADS>>>(
        (const float4*)x, (const float4*)u, (float4*)d_out);
}